// round 6
// baseline (speedup 1.0000x reference)
#include <cuda_runtime.h>
#include <cuda_fp16.h>
#include <math.h>

#define NN    512
#define FF    128
#define HH    256
#define MM    256
#define DEGN  8
#define HISTN 10
#define OO    64
#define PPV   2
#define MAXS  (10*NN)     /* 5120 */
#define NB    148         /* k_main grid */
#define TPB   512
#define CHB   5           /* max chunk batch: static+dynamic smem < 48KB */
#define MAXW  192         /* per-CTA list capacity */
#define NWIN  3           /* 3 x 32 lookahead windows */

/* -------- persistent scratch (device globals; no allocation allowed) ------ */
__device__ float g_hist [NN*HISTN*HH];           // node state ring buffers
__device__ float g_msgs [MAXS*MM];               // message produced by each step
__device__ __align__(16) __half g_A_h [HH*HH];   // A = Wq @ Wk^T (fused q->kq)
__device__ __align__(16) __half g_wr_h[HH*HH];   // fp16 Wr_sum
__device__ __align__(16) __half g_wm_h[2*HH*MM]; // fp16 Wm
__device__ float g_bqk  [HH];                    // Wk @ bq
__device__ int   g_node [MAXS];
__device__ int   g_home [NN];
__device__ int   g_count[NN];
__device__ int   g_done_msg[MAXS];

/* ------------------------- sync helpers ---------------------------------- */
__device__ __forceinline__ int ld_acq(const int* p) {
    int v;
    asm volatile("ld.acquire.gpu.global.b32 %0, [%1];" : "=r"(v) : "l"(p) : "memory");
    return v;
}
__device__ __forceinline__ void st_rel(int* p, int v) {
    asm volatile("st.release.gpu.global.b32 [%0], %1;" :: "l"(p), "r"(v) : "memory");
}

/* ---------------- K1: encode xa -> hist slot0, zero flags ----------------- */
__global__ void k_encode(const float* __restrict__ xa, const float* __restrict__ We,
                         const float* __restrict__ be)
{
    __shared__ float sx[FF];
    int n = blockIdx.x, t = threadIdx.x;
    if (t < FF) sx[t] = xa[n*FF + t];
    __syncthreads();
    float acc = be[t];
    #pragma unroll 4
    for (int f = 0; f < FF; ++f) acc += sx[f] * We[f*HH + t];
    g_hist[((size_t)n*HISTN + 0)*HH + t] = acc;
    if (t < HISTN) g_done_msg[n*HISTN + t] = 0;   // 512*10 == MAXS
}

/* ---------------- K2: Wr_sum (fp16) --------------------------------------- */
__global__ void k_wrsum(const float* __restrict__ Wr)
{
    int i = blockIdx.x, t = threadIdx.x;
    float s = Wr[i*HH + t] + Wr[(HH + i)*HH + t]
            + Wr[(2*HH + i)*HH + t] + Wr[(3*HH + i)*HH + t];
    g_wr_h[i*HH + t] = __float2half(s);
}

/* ---------------- K2b: Wm -> fp16 ----------------------------------------- */
__global__ void k_wmh(const float* __restrict__ Wm)
{
    int b = blockIdx.x, t = threadIdx.x;
    g_wm_h[b*MM + t] = __float2half(Wm[(size_t)b*MM + t]);
}

/* ---------------- K2c: A = Wq @ Wk^T  (fp16 out) -------------------------- */
__global__ void k_prec(const float* __restrict__ Wq, const float* __restrict__ Wk)
{
    __shared__ float a[32][33], bt[32][33];
    int tx = threadIdx.x, ty = threadIdx.y;
    int m0 = blockIdx.y*32, i0 = blockIdx.x*32;
    float acc = 0.f;
    for (int kt = 0; kt < HH; kt += 32) {
        a [ty][tx] = Wq[(m0+ty)*HH + kt + tx];
        bt[tx][ty] = Wk[(i0+ty)*HH + kt + tx];   // bt[h][i]
        __syncthreads();
        #pragma unroll
        for (int k = 0; k < 32; ++k) acc += a[ty][k]*bt[k][tx];
        __syncthreads();
    }
    g_A_h[(m0+ty)*HH + i0 + tx] = __float2half(acc);
}

/* ---------------- K2d: bqk = Wk @ bq -------------------------------------- */
__global__ void k_bqk(const float* __restrict__ Wk, const float* __restrict__ bq)
{
    int w = threadIdx.x >> 5, l = threadIdx.x & 31;
    int r = blockIdx.x*8 + w;
    float p = 0.f;
    #pragma unroll
    for (int k = 0; k < 8; ++k) { int h = l + k*32; p += Wk[r*HH + h]*bq[h]; }
    #pragma unroll
    for (int o = 16; o > 0; o >>= 1) p += __shfl_down_sync(0xffffffffu, p, o);
    if (l == 0) g_bqk[r] = p;
}

/* ------- K3: sequence, visit totals, homes -------------------------------- */
__global__ void k_graph(const int* __restrict__ neighbors, const int* __restrict__ ns_ptr)
{
    __shared__ int sn[MAXS];   // 20 KB
    __shared__ int T[NN], P[NN];
    int t = threadIdx.x;
    int S = *ns_ptr;
    for (int e = t; e < S && e < MAXS; e += TPB) sn[e] = e;
    __syncthreads();
    int known = S;
    while (known < MAXS) {
        long long nx = (long long)S + 8LL*(long long)known;
        int next = (nx > MAXS) ? MAXS : (int)nx;
        for (int e = known + t; e < next; e += TPB) {
            int src = (e - S) >> 3;
            sn[e] = neighbors[sn[src]*DEGN + ((e - S) & 7)];
        }
        __syncthreads();
        known = next;
    }
    T[t] = 0;
    __syncthreads();
    for (int e = t; e < MAXS; e += TPB) atomicAdd(&T[sn[e]], 1);
    __syncthreads();
    P[t] = T[t];
    __syncthreads();
    for (int o = 1; o < NN; o <<= 1) {            // inclusive scan over node ids
        int v = (t >= o) ? P[t-o] : 0;
        __syncthreads();
        P[t] += v;
        __syncthreads();
    }
    {
        int excl = P[t] - T[t];
        g_home[t]  = (int)(((long long)excl * NB) / MAXS);
        g_count[t] = 1 + T[t];
    }
    for (int e = t; e < MAXS; e += TPB) g_node[e] = sn[e];
}

/* ---------------- K4: persistent out-of-order home-CTA processor ---------- */
__global__ void __launch_bounds__(TPB)
k_main(const float* __restrict__ first_message,
       const float* __restrict__ br, const float* __restrict__ bm,
       const int*   __restrict__ ns_ptr)
{
    extern __shared__ float dyn[];
    float (*s_msg)[MM] = (float(*)[MM]) dyn;                        // CHB*MM
    float (*s_kq )[HH] = (float(*)[HH])(dyn + CHB*MM);              // CHB*HH
    float (*s_ns )[HH] = (float(*)[HH])(dyn + CHB*MM + CHB*HH);     // CHB*HH
    float *s_part = dyn + CHB*MM + 2*CHB*HH;                        // CHB*4*HH
    float *s_vals = s_part + CHB*4*HH;                              // HH

    __shared__ float s_logit[16], s_attn[HISTN];
    __shared__ int   s_cnt[NN];            // per-node visit counts (owned only)
    __shared__ int   s_scan[TPB];
    __shared__ int   s_lstep[MAXW], s_lnode[MAXW], s_lprev[MAXW], s_st[MAXW];
    __shared__ int   s_sel[CHB], s_cs[CHB], s_cn[CHB];
    __shared__ int   s_B, s_head, s_L;
    __shared__ unsigned s_bm;

    const int tid = threadIdx.x;
    const int cta = blockIdx.x;
    const int S   = *ns_ptr;

    /* ---- build this CTA's ordered step list (stable compaction) ---- */
    {
        int e0 = tid*10, cl = 0;
        #pragma unroll
        for (int k = 0; k < 10; ++k)
            if (g_home[g_node[e0+k]] == cta) ++cl;
        s_scan[tid] = cl;
        __syncthreads();
        for (int o = 1; o < TPB; o <<= 1) {
            int v = (tid >= o) ? s_scan[tid-o] : 0;
            __syncthreads();
            s_scan[tid] += v;
            __syncthreads();
        }
        int base = s_scan[tid] - cl;
        #pragma unroll
        for (int k = 0; k < 10; ++k) {
            int e = e0 + k, nd = g_node[e];
            if (g_home[nd] == cta) { s_lstep[base] = e; s_lnode[base] = nd; ++base; }
        }
        if (tid == TPB-1) { s_L = s_scan[TPB-1]; s_head = 0; s_B = 0; }
        for (int n = tid; n < NN; n += TPB) s_cnt[n] = 1;
        __syncthreads();
        const int L = s_L;
        for (int p = tid; p < L; p += TPB) {
            int nd = s_lnode[p], pv = -1;
            for (int q = p-1; q >= 0; --q) if (s_lnode[q] == nd) { pv = q; break; }
            s_lprev[p] = pv;
            s_st[p] = 0;
        }
        __syncthreads();
    }
    const int L = s_L;

    while (true) {
        if (tid == 0) {
            int h = s_head;
            while (h < L && s_st[h]) ++h;
            s_head = h;
            s_B = 0;
        }
        __syncthreads();
        const int head = s_head;
        if (head >= L) break;

        /* ---- select up to CHB ready steps from lookahead windows ---- */
        for (int w = 0; w < NWIN; ++w) {
            int base = head + w*32;
            if (base >= L) break;
            if (tid < 32) {
                int p = base + tid;
                bool pend = (p < L) && !s_st[p];
                bool mr = false;
                if (pend) {
                    int s = s_lstep[p];
                    mr = (s < S) || (ld_acq(&g_done_msg[(s-S)>>3]) != 0);
                }
                unsigned bm = __ballot_sync(0xffffffffu, pend && mr);
                if (tid == 0) s_bm = bm;
            }
            __syncthreads();
            if (tid == 0) {
                int B = s_B;
                unsigned bm = s_bm;
                for (int i = 0; i < 32 && B < CHB; ++i) {
                    if (!((bm >> i) & 1)) continue;
                    int p = base + i;
                    int pv = s_lprev[p];
                    bool ok = (pv < 0) || s_st[pv];
                    if (!ok)
                        for (int b = 0; b < B; ++b)
                            if (s_sel[b] == pv) { ok = true; break; }
                    if (ok) s_sel[B++] = p;
                }
                s_B = B;
            }
            __syncthreads();
            if (s_B >= CHB) break;
        }
        if (s_B == 0 && tid == 0) {          /* head is the only blocker */
            int s = s_lstep[head];
            if (s >= S) { int sr = (s-S) >> 3; while (ld_acq(&g_done_msg[sr]) == 0) {} }
            s_sel[0] = head;
            s_B = 1;
        }
        __syncthreads();
        const int B = s_B;
        if (tid < B) { int p = s_sel[tid]; s_cs[tid] = s_lstep[p]; s_cn[tid] = s_lnode[p]; }
        __syncthreads();

        /* ---- load chunk messages (2 per pass with 512 threads) ---- */
        for (int b = tid >> 8; b < B; b += 2) {
            int c = tid & 255;
            int s = s_cs[b];
            s_msg[b][c] = (s < S)
                ? __ldg(first_message + (size_t)s*MM + c)
                : __ldcg(g_msgs + (size_t)((s - S) >> 3)*MM + c);
        }
        __syncthreads();

        /* ---- batched kq = msg @ A + bqk ---- */
        {
            const int g4 = tid >> 7, c2 = tid & 127;
            const __half2* W = (const __half2*)g_A_h;
            float2 acc[CHB];
            #pragma unroll
            for (int b = 0; b < CHB; ++b) acc[b] = make_float2(0.f, 0.f);
            const int i0 = g4*64;
            #pragma unroll 4
            for (int i = i0; i < i0 + 64; ++i) {
                float2 w = __half22float2(W[i*128 + c2]);
                #pragma unroll
                for (int b = 0; b < CHB; ++b) {
                    float x = s_msg[b][i];
                    acc[b].x += x*w.x; acc[b].y += x*w.y;
                }
            }
            #pragma unroll
            for (int b = 0; b < CHB; ++b)
                ((float2*)s_part)[(b*4 + g4)*128 + c2] = acc[b];
            __syncthreads();
            if (tid < HH) {
                for (int b = 0; b < B; ++b) {
                    float r = g_bqk[tid];
                    #pragma unroll
                    for (int g = 0; g < 4; ++g) r += s_part[(b*4+g)*HH + tid];
                    s_kq[b][tid] = r;
                }
            }
            __syncthreads();
        }

        /* ---- serial per-step: attention + Wr ---- */
        for (int j = 0; j < B; ++j) {
            const int nd   = s_cn[j];
            const int cnt  = s_cnt[nd];
            const int nv   = (cnt < HISTN) ? cnt : HISTN;
            const int slot = cnt % HISTN;
            const int wid = tid >> 5, lid = tid & 31;
            if (wid < nv) {
                const float* hp = g_hist + ((size_t)nd*HISTN + wid)*HH;
                float p = 0.f;
                #pragma unroll
                for (int k = 0; k < 8; ++k) { int h = lid + k*32; p += hp[h]*s_kq[j][h]; }
                #pragma unroll
                for (int o = 16; o > 0; o >>= 1) p += __shfl_down_sync(0xffffffffu, p, o);
                if (lid == 0) s_logit[wid] = p * 0.0625f;
            }
            __syncthreads();
            if (tid == 0) {
                float m = -1e30f;
                for (int k = 0; k < nv; ++k) m = fmaxf(m, s_logit[k]);
                float sum = 0.f;
                for (int k = 0; k < nv; ++k) { float e = __expf(s_logit[k]-m); s_attn[k]=e; sum+=e; }
                float inv = 1.f / sum;
                for (int k = 0; k < nv; ++k) s_attn[k] *= inv;
            }
            __syncthreads();
            if (tid < HH) {
                float v = 0.f;
                const float* hp = g_hist + (size_t)nd*HISTN*HH + tid;
                #pragma unroll 2
                for (int k = 0; k < nv; ++k) v += s_attn[k]*hp[k*HH];
                s_vals[tid] = v;
            }
            __syncthreads();
            {   /* Wr matvec (single vector) */
                const int g4 = tid >> 7, c2 = tid & 127;
                const __half2* W = (const __half2*)g_wr_h;
                float2 acc = make_float2(0.f, 0.f);
                const int i0 = g4*64;
                #pragma unroll 8
                for (int i = i0; i < i0 + 64; ++i) {
                    float2 w = __half22float2(W[i*128 + c2]);
                    float x = s_vals[i];
                    acc.x += x*w.x; acc.y += x*w.y;
                }
                ((float2*)s_part)[g4*128 + c2] = acc;
                __syncthreads();
                if (tid < HH) {
                    float r = __ldg(br + tid);
                    #pragma unroll
                    for (int g = 0; g < 4; ++g) r += s_part[g*HH + tid];
                    s_ns[j][tid] = r;
                    g_hist[((size_t)nd*HISTN + slot)*HH + tid] = r;
                }
                if (tid == TPB-1) s_cnt[nd] = cnt + 1;
                __syncthreads();
            }
        }

        /* ---- batched Wm: [ns,msg] @ Wm + bm -> publish msgs ---- */
        {
            const int g4 = tid >> 7, c2 = tid & 127;
            const __half2* W = (const __half2*)g_wm_h;
            const float* xs[CHB];
            #pragma unroll
            for (int b = 0; b < CHB; ++b)
                xs[b] = (g4 < 2) ? (s_ns[b] + g4*128) : (s_msg[b] + (g4-2)*128);
            float2 acc[CHB];
            #pragma unroll
            for (int b = 0; b < CHB; ++b) acc[b] = make_float2(0.f, 0.f);
            const int i0 = g4*128;
            #pragma unroll 2
            for (int ii = 0; ii < 128; ++ii) {
                float2 w = __half22float2(W[(i0+ii)*128 + c2]);
                #pragma unroll
                for (int b = 0; b < CHB; ++b) {
                    float x = xs[b][ii];
                    acc[b].x += x*w.x; acc[b].y += x*w.y;
                }
            }
            #pragma unroll
            for (int b = 0; b < CHB; ++b)
                ((float2*)s_part)[(b*4 + g4)*128 + c2] = acc[b];
            __syncthreads();
            if (tid < MM) {
                for (int b = 0; b < B; ++b) {
                    float r = __ldg(bm + tid);
                    #pragma unroll
                    for (int g = 0; g < 4; ++g) r += s_part[(b*4+g)*MM + tid];
                    g_msgs[(size_t)s_cs[b]*MM + tid] = r;
                }
            }
            __syncthreads();
            if (tid == 0)
                for (int b = 0; b < B; ++b) st_rel(&g_done_msg[s_cs[b]], 1);
            if (tid < B) s_st[s_sel[tid]] = 1;
        }
        __syncthreads();
    }
}

/* ---------------- K5: decoder + log_softmax ------------------------------- */
__global__ void k_out(const float* __restrict__ Wd, const float* __restrict__ bd,
                      float* __restrict__ out)
{
    __shared__ float s_fin[HH];
    __shared__ float s_log[PPV*OO];
    int n = blockIdx.x, t = threadIdx.x;     /* 128 threads */
    int cnt  = g_count[n];
    int slot = (cnt - 1) % HISTN;
    s_fin[t]       = g_hist[((size_t)n*HISTN + slot)*HH + t];
    s_fin[t + 128] = g_hist[((size_t)n*HISTN + slot)*HH + t + 128];
    __syncthreads();
    int p = t >> 6, o = t & 63;
    float acc = bd[p*OO + o];
    #pragma unroll 4
    for (int h = 0; h < HH; ++h) acc += s_fin[h]*Wd[((size_t)p*HH + h)*OO + o];
    s_log[t] = acc;
    __syncthreads();
    float m = -1e30f;
    for (int k = 0; k < OO; ++k) m = fmaxf(m, s_log[p*OO + k]);
    float sum = 0.f;
    for (int k = 0; k < OO; ++k) sum += expf(s_log[p*OO + k] - m);
    out[((size_t)p*NN + n)*OO + o] = acc - m - logf(sum);
}

/* -------------------------------------------------------------------------- */
extern "C" void kernel_launch(void* const* d_in, const int* in_sizes, int n_in,
                              void* d_out, int out_size)
{
    const float* xa  = (const float*)d_in[0];
    const int*   nbr = (const int*)  d_in[1];
    const float* fm  = (const float*)d_in[2];
    const float* We  = (const float*)d_in[3];
    const float* be  = (const float*)d_in[4];
    const float* Wq  = (const float*)d_in[5];
    const float* bq  = (const float*)d_in[6];
    const float* Wk  = (const float*)d_in[7];
    /* d_in[8] = bk cancels in softmax */
    const float* Wr  = (const float*)d_in[9];
    const float* br  = (const float*)d_in[10];
    const float* Wm  = (const float*)d_in[11];
    const float* bm  = (const float*)d_in[12];
    const float* Wd  = (const float*)d_in[13];
    const float* bd  = (const float*)d_in[14];
    const int*   nS  = (const int*)  d_in[15];

    /* dynamic smem (CHB=5) = 36,864 B; k_main static smem ~= 7.4 KB;
       total < 48 KB default limit -> no attribute call needed. */
    const int dyn_bytes = (CHB*MM + 2*CHB*HH + CHB*4*HH + HH) * (int)sizeof(float);

    k_encode<<<NN, HH>>>(xa, We, be);
    k_wrsum <<<HH, HH>>>(Wr);
    k_wmh   <<<2*HH, MM>>>(Wm);
    {
        dim3 g(8, 8), b(32, 32);
        k_prec<<<g, b>>>(Wq, Wk);
    }
    k_bqk   <<<8, 256>>>(Wk, bq);
    k_graph <<<1, TPB>>>(nbr, nS);
    k_main  <<<NB, TPB, dyn_bytes>>>(fm, br, bm, nS);
    k_out   <<<NN, 128>>>(Wd, bd, (float*)d_out);
}